// round 8
// baseline (speedup 1.0000x reference)
#include <cuda_runtime.h>

// Problem constants (fixed by the reference setup_inputs)
#define BB 64
#define SS 2048
#define DD 768
#define DD4 192          // DD / 4 (float4)
#define POOL 32
#define LL 8
#define TOPK 4
#define PROMPT_ROWS 41   // L + TOPK*L + 1
#define ROWS_OUT 2089    // PROMPT_ROWS + SS
#define SCHUNK 64
#define NCHUNK 32        // SS / SCHUNK -> grid 2048 (measured-best config)
#define EPSV 1e-12f

// Scratch (no allocations allowed in kernel_launch)
__device__ float g_partial[NCHUNK * BB * DD];   // ~6.3 MB

// ---------------------------------------------------------------------------
// Kernel 1: stream-copy x -> out tail, fused with per-(chunk,b,d) partial
// sums. EXACT R1 configuration (measured 119.4us @ 80.6% DRAM). Do not touch.
// grid = (NCHUNK, BB) = 2048 blocks, block = 192 threads.
// ---------------------------------------------------------------------------
__global__ void k_copy_reduce(const float4* __restrict__ x,
                              float4* __restrict__ out) {
    const int b     = blockIdx.y;
    const int chunk = blockIdx.x;
    const int d4    = threadIdx.x;                   // 0..191

    const float4* xp = x   + ((size_t)b * SS + (size_t)chunk * SCHUNK) * DD4 + d4;
    float4*       op = out + ((size_t)b * ROWS_OUT + PROMPT_ROWS
                              + (size_t)chunk * SCHUNK) * DD4 + d4;

    float4 acc = make_float4(0.f, 0.f, 0.f, 0.f);
    #pragma unroll 8
    for (int s = 0; s < SCHUNK; s++) {
        float4 v = xp[(size_t)s * DD4];
        op[(size_t)s * DD4] = v;
        acc.x += v.x; acc.y += v.y; acc.z += v.z; acc.w += v.w;
    }
    ((float4*)g_partial)[((size_t)chunk * BB + b) * DD4 + d4] = acc;
}

// ---------------------------------------------------------------------------
// Kernel 2: per batch — float4 2D-parallel partial reduce (warps 0-23) with
// concurrent key-norm computation (warps 24-31), sims (q-norm dropped: a
// positive per-batch factor cannot change ordering), warp-argmax top-4,
// write all 41 prompt rows.  grid = BB, block = 1024.
// ---------------------------------------------------------------------------
__global__ void k_topk_prompts(const float* __restrict__ keys,
                               const float4* __restrict__ gp,
                               const float4* __restrict__ ep,
                               const float4* __restrict__ cls,
                               const int* __restrict__ task_id,
                               float4* __restrict__ out) {
    __shared__ float4 part[4 * DD4];   // 12 KB: 4 chunk-groups x 192 float4
    __shared__ float  q[DD];
    __shared__ float  kk_s[POOL];
    __shared__ float  sims[POOL];
    __shared__ int    topidx[TOPK];

    const int b = blockIdx.x;
    const int t = threadIdx.x;
    const int w = t >> 5, lane = t & 31;

    if (t < 768) {
        // Phase A (warps 0-23): 2D reduce. g = chunk-group (8 chunks each),
        // d4 = float4 column. 8 independent 32B coalesced loads per thread.
        const int g  = t / DD4;          // 0..3
        const int d4 = t - g * DD4;      // 0..191
        const float4* base = (const float4*)g_partial
                           + ((size_t)(g * 8) * BB + b) * DD4 + d4;
        float4 acc = make_float4(0.f, 0.f, 0.f, 0.f);
        #pragma unroll
        for (int c = 0; c < 8; c++) {
            const float4 v = base[(size_t)c * BB * DD4];
            acc.x += v.x; acc.y += v.y; acc.z += v.z; acc.w += v.w;
        }
        part[g * DD4 + d4] = acc;
    } else {
        // Phase A' (warps 24-31): key squared norms, 4 pools per warp.
        const int wn = w - 24;           // 0..7
        #pragma unroll
        for (int pp = 0; pp < 4; pp++) {
            const int p = wn * 4 + pp;
            float a = 0.f;
            #pragma unroll
            for (int d = lane; d < DD; d += 32) {
                const float k = keys[(size_t)p * DD + d];
                a += k * k;
            }
            #pragma unroll
            for (int o = 16; o > 0; o >>= 1)
                a += __shfl_xor_sync(0xffffffffu, a, o);
            if (lane == 0) kk_s[p] = a;
        }
    }
    __syncthreads();

    // Combine the 4 chunk-groups (fixed order -> deterministic)
    if (t < DD4) {
        const float4 a0 = part[t], a1 = part[DD4 + t],
                     a2 = part[2 * DD4 + t], a3 = part[3 * DD4 + t];
        float4 s;
        s.x = (a0.x + a1.x) + (a2.x + a3.x);
        s.y = (a0.y + a1.y) + (a2.y + a3.y);
        s.z = (a0.z + a1.z) + (a2.z + a3.z);
        s.w = (a0.w + a1.w) + (a2.w + a3.w);
        ((float4*)q)[t] = s;
    }
    __syncthreads();

    // Phase B: 32 warps, one pool each: sims[p] = (q.k_p)*rsqrt(kk_p+eps)
    {
        float aqk = 0.f;
        #pragma unroll
        for (int d = lane; d < DD; d += 32)
            aqk += q[d] * keys[(size_t)w * DD + d];
        #pragma unroll
        for (int o = 16; o > 0; o >>= 1)
            aqk += __shfl_xor_sync(0xffffffffu, aqk, o);
        if (lane == 0) sims[w] = aqk * rsqrtf(kk_s[w] + EPSV);
    }
    __syncthreads();

    // Warp 0: top-4 via warp argmax (desc, lowest index on tie)
    if (w == 0) {
        float v = sims[lane];
        #pragma unroll
        for (int k = 0; k < TOPK; k++) {
            float bv = v; int bi = lane;
            #pragma unroll
            for (int o = 16; o > 0; o >>= 1) {
                const float ov = __shfl_xor_sync(0xffffffffu, bv, o);
                const int   oi = __shfl_xor_sync(0xffffffffu, bi, o);
                if (ov > bv || (ov == bv && oi < bi)) { bv = ov; bi = oi; }
            }
            if (lane == 0) topidx[k] = bi;
            if (lane == bi) v = -3.402823e38f;   // remove winner
        }
    }
    __syncthreads();

    // Phase D: write all 41 prompt rows (7872 float4, ~8/thread)
    const int task = task_id[0];
    float4* ob = out + (size_t)b * ROWS_OUT * DD4;
    for (int idx = t; idx < PROMPT_ROWS * DD4; idx += 1024) {
        const int r  = idx / DD4;
        const int d4 = idx - r * DD4;
        const float4* src;
        if (r < LL) {
            src = gp + ((size_t)task * LL + r) * DD4;
        } else if (r < LL + TOPK * LL) {
            const int rr = r - LL;
            src = ep + ((size_t)topidx[rr >> 3] * LL + (rr & 7)) * DD4;
        } else {
            src = cls;
        }
        ob[(size_t)r * DD4 + d4] = src[d4];
    }
}

// ---------------------------------------------------------------------------
extern "C" void kernel_launch(void* const* d_in, const int* in_sizes, int n_in,
                              void* d_out, int out_size) {
    const float4* x   = (const float4*)d_in[0];   // [64,2048,768]
    const float4* gp  = (const float4*)d_in[1];   // [10,8,768]
    const float4* ep  = (const float4*)d_in[2];   // [32,8,768]
    const float*  key = (const float*) d_in[3];   // [32,768]
    const float4* cls = (const float4*)d_in[4];   // [1,1,768]
    const int*    tid = (const int*)   d_in[5];   // scalar task_id
    float4* out = (float4*)d_out;

    k_copy_reduce<<<dim3(NCHUNK, BB), 192>>>(x, out);
    k_topk_prompts<<<BB, 1024>>>(key, gp, ep, cls, tid, out);
}

// round 9
// speedup vs baseline: 1.0226x; 1.0226x over previous
#include <cuda_runtime.h>

// Problem constants (fixed by the reference setup_inputs)
#define BB 64
#define SS 2048
#define DD 768
#define DD4 192          // DD / 4 (float4)
#define POOL 32
#define LL 8
#define TOPK 4
#define PROMPT_ROWS 41   // L + TOPK*L + 1
#define ROWS_OUT 2089    // PROMPT_ROWS + SS
#define SCHUNK 64
#define NCHUNK 32        // SS / SCHUNK -> grid 2048 (measured-best config)
#define EPSV 1e-12f

// Scratch (no allocations allowed in kernel_launch)
__device__ float g_partial[NCHUNK * BB * DD];   // ~6.3 MB

// ---------------------------------------------------------------------------
// Kernel 1: stream-copy x -> out tail + per-(chunk,b,d) partial sums.
// Hot loop identical to measured-best R1 (119.4us @ 80.6% DRAM).
// Signals programmatic launch completion after its stores so the dependent
// kernel can begin its prologue during this kernel's drain.
// grid = (NCHUNK, BB) = 2048 blocks, block = 192 threads.
// ---------------------------------------------------------------------------
__global__ void k_copy_reduce(const float4* __restrict__ x,
                              float4* __restrict__ out) {
    const int b     = blockIdx.y;
    const int chunk = blockIdx.x;
    const int d4    = threadIdx.x;                   // 0..191

    const float4* xp = x   + ((size_t)b * SS + (size_t)chunk * SCHUNK) * DD4 + d4;
    float4*       op = out + ((size_t)b * ROWS_OUT + PROMPT_ROWS
                              + (size_t)chunk * SCHUNK) * DD4 + d4;

    float4 acc = make_float4(0.f, 0.f, 0.f, 0.f);
    #pragma unroll 8
    for (int s = 0; s < SCHUNK; s++) {
        float4 v = xp[(size_t)s * DD4];
        op[(size_t)s * DD4] = v;
        acc.x += v.x; acc.y += v.y; acc.z += v.z; acc.w += v.w;
    }
    ((float4*)g_partial)[((size_t)chunk * BB + b) * DD4 + d4] = acc;

#if __CUDA_ARCH__ >= 900
    cudaTriggerProgrammaticLaunchCompletion();
#endif
}

// ---------------------------------------------------------------------------
// Kernel 2 (PDL): prologue (pre-sync) = key norms + static prompt rows +
// e_prompts L2 prefetch; then grid-dependency sync; then partial reduce,
// sims (q-norm dropped: positive per-batch factor cannot change ordering),
// warp-argmax top-4, write the 32 e-prompt rows.  grid = BB, block = 1024.
// ---------------------------------------------------------------------------
__global__ void k_topk_prompts(const float* __restrict__ keys,
                               const float4* __restrict__ gp,
                               const float4* __restrict__ ep,
                               const float4* __restrict__ cls,
                               const int* __restrict__ task_id,
                               float4* __restrict__ out) {
    __shared__ float4 part[4 * DD4];   // 12 KB
    __shared__ float  q[DD];
    __shared__ float  kk_s[POOL];
    __shared__ float  sims[POOL];
    __shared__ int    topidx[TOPK];

    const int b = blockIdx.x;
    const int t = threadIdx.x;
    const int w = t >> 5, lane = t & 31;
    float4* ob = out + (size_t)b * ROWS_OUT * DD4;

    // ---------------- prologue: independent of kernel 1 ----------------
    // (a) key squared norms: warps 0-7, 4 pools each
    if (w < 8) {
        #pragma unroll
        for (int pp = 0; pp < 4; pp++) {
            const int p = w * 4 + pp;
            float a = 0.f;
            #pragma unroll
            for (int d = lane; d < DD; d += 32) {
                const float k = keys[(size_t)p * DD + d];
                a += k * k;
            }
            #pragma unroll
            for (int o = 16; o > 0; o >>= 1)
                a += __shfl_xor_sync(0xffffffffu, a, o);
            if (lane == 0) kk_s[p] = a;
        }
    }
    // (b) static prompt rows: 0..7 = g_prompts[task], 40 = cls (disjoint
    //     from kernel 1's output region -> safe to write pre-sync)
    {
        const int task = task_id[0];
        for (int idx = t; idx < 9 * DD4; idx += 1024) {
            const int r  = idx / DD4;          // 0..8
            const int d4 = idx - r * DD4;
            if (r < LL)
                ob[(size_t)r * DD4 + d4] = gp[((size_t)task * LL + r) * DD4 + d4];
            else
                ob[(size_t)(PROMPT_ROWS - 1) * DD4 + d4] = cls[d4];
        }
    }
    // (c) warm e_prompts into L2 (768 KB total; 12 KB slice per block)
    if (t < 96) {
        const char* p = (const char*)ep + (size_t)b * 12288 + (size_t)t * 128;
        asm volatile("prefetch.global.L2 [%0];" :: "l"(p));
    }

    // ---------------- wait for kernel 1's partials ----------------
#if __CUDA_ARCH__ >= 900
    cudaGridDependencySynchronize();
#endif

    // Phase A: 2D float4 reduce of the 32 chunk partials (768 threads)
    if (t < 768) {
        const int g  = t / DD4;          // 0..3 (8 chunks each)
        const int d4 = t - g * DD4;      // 0..191
        const float4* base = (const float4*)g_partial
                           + ((size_t)(g * 8) * BB + b) * DD4 + d4;
        float4 acc = make_float4(0.f, 0.f, 0.f, 0.f);
        #pragma unroll
        for (int c = 0; c < 8; c++) {
            const float4 v = base[(size_t)c * BB * DD4];
            acc.x += v.x; acc.y += v.y; acc.z += v.z; acc.w += v.w;
        }
        part[g * DD4 + d4] = acc;
    }
    __syncthreads();
    if (t < DD4) {
        const float4 a0 = part[t], a1 = part[DD4 + t],
                     a2 = part[2 * DD4 + t], a3 = part[3 * DD4 + t];
        float4 s;
        s.x = (a0.x + a1.x) + (a2.x + a3.x);
        s.y = (a0.y + a1.y) + (a2.y + a3.y);
        s.z = (a0.z + a1.z) + (a2.z + a3.z);
        s.w = (a0.w + a1.w) + (a2.w + a3.w);
        ((float4*)q)[t] = s;
    }
    __syncthreads();

    // Phase B: 32 warps, one pool each
    {
        float aqk = 0.f;
        #pragma unroll
        for (int d = lane; d < DD; d += 32)
            aqk += q[d] * keys[(size_t)w * DD + d];
        #pragma unroll
        for (int o = 16; o > 0; o >>= 1)
            aqk += __shfl_xor_sync(0xffffffffu, aqk, o);
        if (lane == 0) sims[w] = aqk * rsqrtf(kk_s[w] + EPSV);
    }
    __syncthreads();

    // Phase C: warp 0 top-4 via warp argmax (desc, lowest index on tie)
    if (w == 0) {
        float v = sims[lane];
        #pragma unroll
        for (int k = 0; k < TOPK; k++) {
            float bv = v; int bi = lane;
            #pragma unroll
            for (int o = 16; o > 0; o >>= 1) {
                const float ov = __shfl_xor_sync(0xffffffffu, bv, o);
                const int   oi = __shfl_xor_sync(0xffffffffu, bi, o);
                if (ov > bv || (ov == bv && oi < bi)) { bv = ov; bi = oi; }
            }
            if (lane == 0) topidx[k] = bi;
            if (lane == bi) v = -3.402823e38f;   // remove winner
        }
    }
    __syncthreads();

    // Phase D: write the 32 e-prompt rows (rows 8..39), 6144 float4
    for (int idx = t; idx < POOL * DD4; idx += 1024) {
        const int rr = idx / DD4;          // 0..31
        const int d4 = idx - rr * DD4;
        const float4* src = ep + ((size_t)topidx[rr >> 3] * LL + (rr & 7)) * DD4;
        ob[(size_t)(LL + rr) * DD4 + d4] = src[d4];
    }
}

// ---------------------------------------------------------------------------
extern "C" void kernel_launch(void* const* d_in, const int* in_sizes, int n_in,
                              void* d_out, int out_size) {
    const float4* x   = (const float4*)d_in[0];   // [64,2048,768]
    const float4* gp  = (const float4*)d_in[1];   // [10,8,768]
    const float4* ep  = (const float4*)d_in[2];   // [32,8,768]
    const float*  key = (const float*) d_in[3];   // [32,768]
    const float4* cls = (const float4*)d_in[4];   // [1,1,768]
    const int*    tid = (const int*)   d_in[5];   // scalar task_id
    float4* out = (float4*)d_out;

    k_copy_reduce<<<dim3(NCHUNK, BB), 192>>>(x, out);

    // Dependent launch with programmatic stream serialization (PDL)
    cudaLaunchConfig_t cfg = {};
    cfg.gridDim  = dim3(BB);
    cfg.blockDim = dim3(1024);
    cfg.dynamicSmemBytes = 0;
    cfg.stream = 0;
    cudaLaunchAttribute attr[1];
    attr[0].id = cudaLaunchAttributeProgrammaticStreamSerialization;
    attr[0].val.programmaticStreamSerializationAllowed = 1;
    cfg.attrs = attr;
    cfg.numAttrs = 1;
    cudaLaunchKernelEx(&cfg, k_topk_prompts, key, gp, ep, cls, tid, out);
}